// round 3
// baseline (speedup 1.0000x reference)
#include <cuda_runtime.h>
#include <cstdint>

// PScan: Y_t = A_t @ Y_{t-1} + X_t  (Y_0 = X_0), per (b,c) chain.
// Shapes: A,X,Y = [B=4, L=2048, C=16, 16, 16] fp32, row-major.
// Chunked scan (TT=32), cp.async staging, f32x2 FFMA.

#define BB 4
#define LL 2048
#define CC 16
#define TT 32
#define NCHUNK (LL / TT)            // 64
#define CHAINS (BB * CC)            // 64
#define TOTCHUNK (CHAINS * NCHUNK)  // 4096
#define STEP_STRIDE (CC * 256)

typedef unsigned long long u64;

__device__ float g_Pagg[TOTCHUNK * 256];
__device__ float g_Zagg[TOTCHUNK * 256];
__device__ float g_carry[TOTCHUNK * 256];

__device__ __forceinline__ u64 ffma2(u64 a, u64 b, u64 c) {
    u64 d;
    asm("fma.rn.f32x2 %0, %1, %2, %3;" : "=l"(d) : "l"(a), "l"(b), "l"(c));
    return d;
}
__device__ __forceinline__ u64 add2(u64 a, u64 b) {
    u64 d;
    asm("add.rn.f32x2 %0, %1, %2;" : "=l"(d) : "l"(a), "l"(b));
    return d;
}
__device__ __forceinline__ u64 pack2(float lo, float hi) {
    u64 d;
    asm("mov.b64 %0, {%1, %2};" : "=l"(d) : "f"(lo), "f"(hi));
    return d;
}
__device__ __forceinline__ void unpack2(u64 v, float& lo, float& hi) {
    asm("mov.b64 {%0, %1}, %2;" : "=f"(lo), "=f"(hi) : "l"(v));
}

__device__ __forceinline__ void cp16(float* smem_dst, const float* gsrc) {
    uint32_t s = (uint32_t)__cvta_generic_to_shared(smem_dst);
    asm volatile("cp.async.ca.shared.global [%0], [%1], 16;\n" :: "r"(s), "l"(gsrc));
}
#define CP_COMMIT() asm volatile("cp.async.commit_group;\n" ::: "memory")
#define CP_WAIT1()  asm volatile("cp.async.wait_group 1;\n" ::: "memory")
#define CP_WAIT0()  asm volatile("cp.async.wait_group 0;\n" ::: "memory")

// 16x16 fp32 matvec step for one column: yn = A*y (+x), split accumulators.
__device__ __forceinline__ void matstep(const float* As, const u64* ypk, float* yn)
{
#pragma unroll
    for (int i = 0; i < 16; i++) {
        const ulonglong2* ar = (const ulonglong2*)(As + i * 16);
        ulonglong2 a0 = ar[0], a1 = ar[1], a2 = ar[2], a3 = ar[3];
        u64 acc0 = 0ull, acc1 = 0ull;
        acc0 = ffma2(a0.x, ypk[0], acc0);
        acc1 = ffma2(a2.x, ypk[4], acc1);
        acc0 = ffma2(a0.y, ypk[1], acc0);
        acc1 = ffma2(a2.y, ypk[5], acc1);
        acc0 = ffma2(a1.x, ypk[2], acc0);
        acc1 = ffma2(a3.x, ypk[6], acc1);
        acc0 = ffma2(a1.y, ypk[3], acc0);
        acc1 = ffma2(a3.y, ypk[7], acc1);
        u64 s = add2(acc0, acc1);
        float lo, hi;
        unpack2(s, lo, hi);
        yn[i] = lo + hi;
    }
}

// ============================================================================
// Phase 1: chunk aggregates. One warp per chunk; 64-thread blocks.
// Lanes 0-15: Z columns (init 0, + X). Lanes 16-31: P columns (init I).
// A_t/X_t double-buffered in smem via cp.async.
// ============================================================================
__global__ void __launch_bounds__(64) phase1_kernel(
    const float* __restrict__ A, const float* __restrict__ X)
{
    __shared__ __align__(16) float sm[2][2][512];  // [warp][buf][A:256|X:256]

    const int wid  = threadIdx.x >> 5;
    const int lane = threadIdx.x & 31;
    const int w    = blockIdx.x * 2 + wid;
    const int chain = w / NCHUNK;
    const int chunk = w % NCHUNK;
    const int b = chain >> 4;
    const int c = chain & 15;
    const int t0 = chunk * TT;
    const int col = lane & 15;
    const bool zside = (lane < 16);

    const int base0 = ((b * LL + t0) * CC + c) * 256;
    const float* src = (zside ? A : X) + base0 + col * 4;
    float* dst0 = sm[wid][0] + (zside ? 0 : 256) + col * 4;
    float* dst1 = sm[wid][1] + (zside ? 0 : 256) + col * 4;

    // stage step 0 -> buf 0
#pragma unroll
    for (int q = 0; q < 4; q++) cp16(dst0 + q * 64, src + q * 64);
    CP_COMMIT();

    u64 ypk[8];
#pragma unroll
    for (int m = 0; m < 8; m++) {
        float lo = 0.f, hi = 0.f;
        if (!zside) {
            if (col == 2 * m)     lo = 1.f;
            if (col == 2 * m + 1) hi = 1.f;
        }
        ypk[m] = pack2(lo, hi);
    }

#pragma unroll 1
    for (int t = 0; t < TT; t++) {
        if (t + 1 < TT) {
            const float* s2 = src + (t + 1) * STEP_STRIDE;
            float* dn = (t & 1) ? dst0 : dst1;
#pragma unroll
            for (int q = 0; q < 4; q++) cp16(dn + q * 64, s2 + q * 64);
            CP_COMMIT();
            CP_WAIT1();
        } else {
            CP_WAIT0();
        }
        __syncwarp();

        const float* As = sm[wid][t & 1];
        const float* Xs = As + 256;

        float yn[16];
        matstep(As, ypk, yn);
        if (zside) {
#pragma unroll
            for (int i = 0; i < 16; i++) yn[i] += Xs[i * 16 + col];
        }
#pragma unroll
        for (int m = 0; m < 8; m++) ypk[m] = pack2(yn[2 * m], yn[2 * m + 1]);

        __syncwarp();   // protect buf t&1 before next iter's prefetch
    }

    float* agg = zside ? g_Zagg : g_Pagg;
    const int aggBase = w * 256;
    float cl[16];
#pragma unroll
    for (int m = 0; m < 8; m++) unpack2(ypk[m], cl[2 * m], cl[2 * m + 1]);
#pragma unroll
    for (int i = 0; i < 16; i++) agg[aggBase + i * 16 + col] = cl[i];
}

// ============================================================================
// Phase 2: per-chain scan of 64 chunk aggregates with smem prefetch pipeline.
// ============================================================================
__global__ void phase2_kernel()
{
    __shared__ __align__(16) float sP[2][256];
    __shared__ __align__(16) float sZ[2][256];

    const int chain = blockIdx.x;
    const int lane  = threadIdx.x;
    const int col   = lane & 15;
    const bool zside = (lane < 16);

    {
        const int base = (chain * NCHUNK) * 256;
#pragma unroll
        for (int q = 0; q < 2; q++) {
            *(float4*)(sP[0] + lane * 8 + q * 4) = *(const float4*)(g_Pagg + base + lane * 8 + q * 4);
            *(float4*)(sZ[0] + lane * 8 + q * 4) = *(const float4*)(g_Zagg + base + lane * 8 + q * 4);
        }
    }
    __syncwarp();

    u64 ypk[8];
#pragma unroll
    for (int m = 0; m < 8; m++) ypk[m] = 0ull;

#pragma unroll 1
    for (int cix = 0; cix < NCHUNK; cix++) {
        const int buf = cix & 1;

        if (cix + 1 < NCHUNK) {
            const int nb = (chain * NCHUNK + cix + 1) * 256;
#pragma unroll
            for (int q = 0; q < 2; q++) {
                *(float4*)(sP[buf ^ 1] + lane * 8 + q * 4) = *(const float4*)(g_Pagg + nb + lane * 8 + q * 4);
                *(float4*)(sZ[buf ^ 1] + lane * 8 + q * 4) = *(const float4*)(g_Zagg + nb + lane * 8 + q * 4);
            }
        }

        if (zside) {
            const int base = (chain * NCHUNK + cix) * 256;
            float cl[16];
#pragma unroll
            for (int m = 0; m < 8; m++) unpack2(ypk[m], cl[2 * m], cl[2 * m + 1]);
#pragma unroll
            for (int i = 0; i < 16; i++) g_carry[base + i * 16 + col] = cl[i];

            float yn[16];
            matstep(sP[buf], ypk, yn);
#pragma unroll
            for (int i = 0; i < 16; i++) yn[i] += sZ[buf][i * 16 + col];
#pragma unroll
            for (int m = 0; m < 8; m++) ypk[m] = pack2(yn[2 * m], yn[2 * m + 1]);
        }
        __syncwarp();
    }
}

// ============================================================================
// Phase 3: final pass. One warp per chunk; lanes 0-15 run the recurrence from
// the carry; output transposed through padded smem -> coalesced STG.128.
// ============================================================================
#define YP 18

__global__ void __launch_bounds__(64) phase3_kernel(
    const float* __restrict__ A, const float* __restrict__ X,
    float* __restrict__ Y)
{
    __shared__ __align__(16) float sm[2][2][512];
    __shared__ __align__(16) float sy[2][2][16 * YP];

    const int wid  = threadIdx.x >> 5;
    const int lane = threadIdx.x & 31;
    const int w    = blockIdx.x * 2 + wid;
    const int chain = w / NCHUNK;
    const int chunk = w % NCHUNK;
    const int b = chain >> 4;
    const int c = chain & 15;
    const int t0 = chunk * TT;
    const int col = lane & 15;
    const bool zside = (lane < 16);

    const int base0 = ((b * LL + t0) * CC + c) * 256;
    const float* src = (zside ? A : X) + base0 + col * 4;
    float* dst0 = sm[wid][0] + (zside ? 0 : 256) + col * 4;
    float* dst1 = sm[wid][1] + (zside ? 0 : 256) + col * 4;

#pragma unroll
    for (int q = 0; q < 4; q++) cp16(dst0 + q * 64, src + q * 64);
    CP_COMMIT();

    // init state from carry (state before this chunk)
    u64 ypk[8];
    {
        const int cb = w * 256;
        float cl[16];
#pragma unroll
        for (int i = 0; i < 16; i++)
            cl[i] = zside ? g_carry[cb + i * 16 + col] : 0.f;
#pragma unroll
        for (int m = 0; m < 8; m++) ypk[m] = pack2(cl[2 * m], cl[2 * m + 1]);
    }

    const int e0a = lane * 4;
    const int e0b = 128 + lane * 4;

#pragma unroll 1
    for (int t = 0; t < TT; t++) {
        if (t + 1 < TT) {
            const float* s2 = src + (t + 1) * STEP_STRIDE;
            float* dn = (t & 1) ? dst0 : dst1;
#pragma unroll
            for (int q = 0; q < 4; q++) cp16(dn + q * 64, s2 + q * 64);
            CP_COMMIT();
            CP_WAIT1();
        } else {
            CP_WAIT0();
        }
        __syncwarp();

        const float* As = sm[wid][t & 1];
        const float* Xs = As + 256;
        float* Ys = sy[wid][t & 1];

        if (zside) {
            float yn[16];
            matstep(As, ypk, yn);
#pragma unroll
            for (int i = 0; i < 16; i++) yn[i] += Xs[i * 16 + col];
#pragma unroll
            for (int m = 0; m < 8; m++) ypk[m] = pack2(yn[2 * m], yn[2 * m + 1]);

            u64* yc = (u64*)(Ys + col * YP);
#pragma unroll
            for (int m = 0; m < 8; m++) yc[m] = ypk[m];
        }
        __syncwarp();

        // coalesced write of Y_t (1KB contiguous) by all 32 lanes
        {
            float* out = Y + base0 + t * STEP_STRIDE;
            float4 v;
            int i = e0a >> 4, c0 = e0a & 15;
            v.x = Ys[(c0 + 0) * YP + i];
            v.y = Ys[(c0 + 1) * YP + i];
            v.z = Ys[(c0 + 2) * YP + i];
            v.w = Ys[(c0 + 3) * YP + i];
            *(float4*)(out + e0a) = v;
            i = e0b >> 4; c0 = e0b & 15;
            v.x = Ys[(c0 + 0) * YP + i];
            v.y = Ys[(c0 + 1) * YP + i];
            v.z = Ys[(c0 + 2) * YP + i];
            v.w = Ys[(c0 + 3) * YP + i];
            *(float4*)(out + e0b) = v;
        }
    }
}

// ============================================================================
extern "C" void kernel_launch(void* const* d_in, const int* in_sizes, int n_in,
                              void* d_out, int out_size)
{
    const float* A = (const float*)d_in[0];
    const float* X = (const float*)d_in[1];
    float* Y = (float*)d_out;

    phase1_kernel<<<TOTCHUNK / 2, 64>>>(A, X);
    phase2_kernel<<<CHAINS, 32>>>();
    phase3_kernel<<<TOTCHUNK / 2, 64>>>(A, X, Y);
}

// round 4
// speedup vs baseline: 1.0494x; 1.0494x over previous
#include <cuda_runtime.h>
#include <cstdint>

// PScan: Y_t = A_t @ Y_{t-1} + X_t  (Y_0 = X_0), per (b,c) chain.
// Shapes: A,X,Y = [B=4, L=2048, C=16, 16, 16] fp32, row-major.
// Chunked scan (TT=32), cp.async staging, f32x2 FFMA, split-k half-warps.
// Lane (j, h): column j, k-half h. Each lane reads only its 8-float k-half of
// each A row; halves exchange partials via shfl.xor(16).

#define BB 4
#define LL 2048
#define CC 16
#define TT 32
#define NCHUNK (LL / TT)            // 64
#define CHAINS (BB * CC)            // 64
#define TOTCHUNK (CHAINS * NCHUNK)  // 4096
#define STEP_STRIDE (CC * 256)

typedef unsigned long long u64;

__device__ float g_Pagg[TOTCHUNK * 256];
__device__ float g_Zagg[TOTCHUNK * 256];
__device__ float g_carry[TOTCHUNK * 256];

__device__ __forceinline__ u64 ffma2(u64 a, u64 b, u64 c) {
    u64 d;
    asm("fma.rn.f32x2 %0, %1, %2, %3;" : "=l"(d) : "l"(a), "l"(b), "l"(c));
    return d;
}
__device__ __forceinline__ u64 add2(u64 a, u64 b) {
    u64 d;
    asm("add.rn.f32x2 %0, %1, %2;" : "=l"(d) : "l"(a), "l"(b));
    return d;
}
__device__ __forceinline__ u64 pack2(float lo, float hi) {
    u64 d;
    asm("mov.b64 %0, {%1, %2};" : "=l"(d) : "f"(lo), "f"(hi));
    return d;
}
__device__ __forceinline__ void unpack2(u64 v, float& lo, float& hi) {
    asm("mov.b64 {%0, %1}, %2;" : "=f"(lo), "=f"(hi) : "l"(v));
}

__device__ __forceinline__ void cp16(float* smem_dst, const float* gsrc) {
    uint32_t s = (uint32_t)__cvta_generic_to_shared(smem_dst);
    asm volatile("cp.async.ca.shared.global [%0], [%1], 16;\n" :: "r"(s), "l"(gsrc));
}
#define CP_COMMIT() asm volatile("cp.async.commit_group;\n" ::: "memory")
#define CP_WAIT1()  asm volatile("cp.async.wait_group 1;\n" ::: "memory")
#define CP_WAIT0()  asm volatile("cp.async.wait_group 0;\n" ::: "memory")

// partial dot of one A-row k-half (a0,a1 = 4 f32x2) with packed state st[4]
__device__ __forceinline__ float dot8(ulonglong2 a0, ulonglong2 a1, const u64* st)
{
    u64 acc0 = ffma2(a0.x, st[0], 0ull);
    u64 acc1 = ffma2(a0.y, st[1], 0ull);
    acc0 = ffma2(a1.x, st[2], acc0);
    acc1 = ffma2(a1.y, st[3], acc1);
    float lo, hi;
    unpack2(add2(acc0, acc1), lo, hi);
    return lo + hi;
}

// ============================================================================
// Phase 1: chunk aggregates. One warp per chunk; 64-thread blocks.
// Lane (j,h) computes k-half-h partials of BOTH Z[:,j] and P[:,j];
// halves combined via shfl.xor(16). State kept: rows [8h,8h+8) of column j.
// ============================================================================
__global__ void __launch_bounds__(64) phase1_kernel(
    const float* __restrict__ A, const float* __restrict__ X)
{
    __shared__ __align__(16) float sm[2][2][512];  // [warp][buf][A:256|X:256]

    const int wid  = threadIdx.x >> 5;
    const int lane = threadIdx.x & 31;
    const int w    = blockIdx.x * 2 + wid;
    const int chain = w / NCHUNK;
    const int chunk = w % NCHUNK;
    const int b = chain >> 4;
    const int c = chain & 15;
    const int t0 = chunk * TT;
    const int j = lane & 15;
    const int h = lane >> 4;

    const int base0 = ((b * LL + t0) * CC + c) * 256;
    // staging: h==0 lanes stage A, h==1 lanes stage X
    const float* src = (h == 0 ? A : X) + base0 + j * 4;
    float* dst0 = sm[wid][0] + (h == 0 ? 0 : 256) + j * 4;
    float* dst1 = sm[wid][1] + (h == 0 ? 0 : 256) + j * 4;

#pragma unroll
    for (int q = 0; q < 4; q++) cp16(dst0 + q * 64, src + q * 64);
    CP_COMMIT();

    // state: Z rows [8h..8h+8) of col j (zeros); P same rows of identity
    u64 zst[4], pst[4];
#pragma unroll
    for (int mm = 0; mm < 4; mm++) {
        zst[mm] = 0ull;
        int k0 = 8 * h + 2 * mm;
        pst[mm] = pack2(j == k0 ? 1.f : 0.f, j == k0 + 1 ? 1.f : 0.f);
    }

#pragma unroll 1
    for (int t = 0; t < TT; t++) {
        if (t + 1 < TT) {
            const float* s2 = src + (t + 1) * STEP_STRIDE;
            float* dn = (t & 1) ? dst0 : dst1;
#pragma unroll
            for (int q = 0; q < 4; q++) cp16(dn + q * 64, s2 + q * 64);
            CP_COMMIT();
            CP_WAIT1();
        } else {
            CP_WAIT0();
        }
        __syncwarp();

        const float* As = sm[wid][t & 1];
        const float* Xs = As + 256;
        const float* Ah = As + h * 8;   // this lane's k-half within each row

        float zpL[8], zpH[8], ppL[8], ppH[8];
#pragma unroll
        for (int r = 0; r < 8; r++) {
            ulonglong2 a0 = *(const ulonglong2*)(Ah + r * 16);
            ulonglong2 a1 = *(const ulonglong2*)(Ah + r * 16 + 4);
            zpL[r] = dot8(a0, a1, zst);
            ppL[r] = dot8(a0, a1, pst);
            ulonglong2 b0 = *(const ulonglong2*)(Ah + (8 + r) * 16);
            ulonglong2 b1 = *(const ulonglong2*)(Ah + (8 + r) * 16 + 4);
            zpH[r] = dot8(b0, b1, zst);
            ppH[r] = dot8(b0, b1, pst);
        }

        // combine halves: lane keeps rows [8h, 8h+8)
        float zn[8], pn[8];
#pragma unroll
        for (int r = 0; r < 8; r++) {
            float zsend = h ? zpL[r] : zpH[r];
            float zrecv = __shfl_xor_sync(0xffffffffu, zsend, 16);
            float zown  = h ? zpH[r] : zpL[r];
            float xv = Xs[(8 * h + r) * 16 + j];
            zn[r] = zown + zrecv + xv;

            float psend = h ? ppL[r] : ppH[r];
            float precv = __shfl_xor_sync(0xffffffffu, psend, 16);
            float pown  = h ? ppH[r] : ppL[r];
            pn[r] = pown + precv;
        }
#pragma unroll
        for (int mm = 0; mm < 4; mm++) {
            zst[mm] = pack2(zn[2 * mm], zn[2 * mm + 1]);
            pst[mm] = pack2(pn[2 * mm], pn[2 * mm + 1]);
        }
        __syncwarp();
    }

    // store aggregates (rows [8h,8h+8) of column j)
    const int ab = w * 256;
#pragma unroll
    for (int mm = 0; mm < 4; mm++) {
        const int row = 8 * h + 2 * mm;
        float lo, hi;
        unpack2(zst[mm], lo, hi);
        g_Zagg[ab + row * 16 + j] = lo;
        g_Zagg[ab + (row + 1) * 16 + j] = hi;
        unpack2(pst[mm], lo, hi);
        g_Pagg[ab + row * 16 + j] = lo;
        g_Pagg[ab + (row + 1) * 16 + j] = hi;
    }
}

// ============================================================================
// Phase 2: per-chain scan of 64 chunk aggregates with smem prefetch pipeline.
// ============================================================================
__global__ void phase2_kernel()
{
    __shared__ __align__(16) float sP[2][256];
    __shared__ __align__(16) float sZ[2][256];

    const int chain = blockIdx.x;
    const int lane  = threadIdx.x;
    const int col   = lane & 15;
    const bool zside = (lane < 16);

    {
        const int base = (chain * NCHUNK) * 256;
#pragma unroll
        for (int q = 0; q < 2; q++) {
            *(float4*)(sP[0] + lane * 8 + q * 4) = *(const float4*)(g_Pagg + base + lane * 8 + q * 4);
            *(float4*)(sZ[0] + lane * 8 + q * 4) = *(const float4*)(g_Zagg + base + lane * 8 + q * 4);
        }
    }
    __syncwarp();

    u64 ypk[8];
#pragma unroll
    for (int m = 0; m < 8; m++) ypk[m] = 0ull;

#pragma unroll 1
    for (int cix = 0; cix < NCHUNK; cix++) {
        const int buf = cix & 1;

        if (cix + 1 < NCHUNK) {
            const int nb = (chain * NCHUNK + cix + 1) * 256;
#pragma unroll
            for (int q = 0; q < 2; q++) {
                *(float4*)(sP[buf ^ 1] + lane * 8 + q * 4) = *(const float4*)(g_Pagg + nb + lane * 8 + q * 4);
                *(float4*)(sZ[buf ^ 1] + lane * 8 + q * 4) = *(const float4*)(g_Zagg + nb + lane * 8 + q * 4);
            }
        }

        if (zside) {
            const int base = (chain * NCHUNK + cix) * 256;
            float cl[16];
#pragma unroll
            for (int m = 0; m < 8; m++) unpack2(ypk[m], cl[2 * m], cl[2 * m + 1]);
#pragma unroll
            for (int i = 0; i < 16; i++) g_carry[base + i * 16 + col] = cl[i];

            float yn[16];
#pragma unroll
            for (int i = 0; i < 16; i++) {
                const ulonglong2* pr = (const ulonglong2*)(sP[buf] + i * 16);
                ulonglong2 a0 = pr[0], a1 = pr[1], a2 = pr[2], a3 = pr[3];
                u64 acc0 = ffma2(a0.x, ypk[0], 0ull);
                u64 acc1 = ffma2(a2.x, ypk[4], 0ull);
                acc0 = ffma2(a0.y, ypk[1], acc0);
                acc1 = ffma2(a2.y, ypk[5], acc1);
                acc0 = ffma2(a1.x, ypk[2], acc0);
                acc1 = ffma2(a3.x, ypk[6], acc1);
                acc0 = ffma2(a1.y, ypk[3], acc0);
                acc1 = ffma2(a3.y, ypk[7], acc1);
                float lo, hi;
                unpack2(add2(acc0, acc1), lo, hi);
                yn[i] = lo + hi + sZ[buf][i * 16 + col];
            }
#pragma unroll
            for (int m = 0; m < 8; m++) ypk[m] = pack2(yn[2 * m], yn[2 * m + 1]);
        }
        __syncwarp();
    }
}

// ============================================================================
// Phase 3: final pass, split-k. All 32 lanes compute; Y staged (padded smem
// transpose) and written back as 2 coalesced STG.128 per step.
// ============================================================================
#define YP 18

__global__ void __launch_bounds__(64) phase3_kernel(
    const float* __restrict__ A, const float* __restrict__ X,
    float* __restrict__ Y)
{
    __shared__ __align__(16) float sm[2][2][512];
    __shared__ __align__(16) float sy[2][2][16 * YP];

    const int wid  = threadIdx.x >> 5;
    const int lane = threadIdx.x & 31;
    const int w    = blockIdx.x * 2 + wid;
    const int chain = w / NCHUNK;
    const int chunk = w % NCHUNK;
    const int b = chain >> 4;
    const int c = chain & 15;
    const int t0 = chunk * TT;
    const int j = lane & 15;
    const int h = lane >> 4;

    const int base0 = ((b * LL + t0) * CC + c) * 256;
    const float* src = (h == 0 ? A : X) + base0 + j * 4;
    float* dst0 = sm[wid][0] + (h == 0 ? 0 : 256) + j * 4;
    float* dst1 = sm[wid][1] + (h == 0 ? 0 : 256) + j * 4;

#pragma unroll
    for (int q = 0; q < 4; q++) cp16(dst0 + q * 64, src + q * 64);
    CP_COMMIT();

    // init state from carry: rows [8h, 8h+8) of column j
    u64 zst[4];
    {
        const int cb = w * 256;
#pragma unroll
        for (int mm = 0; mm < 4; mm++) {
            const int row = 8 * h + 2 * mm;
            zst[mm] = pack2(g_carry[cb + row * 16 + j],
                            g_carry[cb + (row + 1) * 16 + j]);
        }
    }

    const int e0a = lane * 4;
    const int e0b = 128 + lane * 4;

#pragma unroll 1
    for (int t = 0; t < TT; t++) {
        if (t + 1 < TT) {
            const float* s2 = src + (t + 1) * STEP_STRIDE;
            float* dn = (t & 1) ? dst0 : dst1;
#pragma unroll
            for (int q = 0; q < 4; q++) cp16(dn + q * 64, s2 + q * 64);
            CP_COMMIT();
            CP_WAIT1();
        } else {
            CP_WAIT0();
        }
        __syncwarp();

        const float* As = sm[wid][t & 1];
        const float* Xs = As + 256;
        const float* Ah = As + h * 8;
        float* Ys = sy[wid][t & 1];

        float zpL[8], zpH[8];
#pragma unroll
        for (int r = 0; r < 8; r++) {
            ulonglong2 a0 = *(const ulonglong2*)(Ah + r * 16);
            ulonglong2 a1 = *(const ulonglong2*)(Ah + r * 16 + 4);
            zpL[r] = dot8(a0, a1, zst);
            ulonglong2 b0 = *(const ulonglong2*)(Ah + (8 + r) * 16);
            ulonglong2 b1 = *(const ulonglong2*)(Ah + (8 + r) * 16 + 4);
            zpH[r] = dot8(b0, b1, zst);
        }

        float zn[8];
#pragma unroll
        for (int r = 0; r < 8; r++) {
            float zsend = h ? zpL[r] : zpH[r];
            float zrecv = __shfl_xor_sync(0xffffffffu, zsend, 16);
            float zown  = h ? zpH[r] : zpL[r];
            float xv = Xs[(8 * h + r) * 16 + j];
            zn[r] = zown + zrecv + xv;
        }
#pragma unroll
        for (int mm = 0; mm < 4; mm++)
            zst[mm] = pack2(zn[2 * mm], zn[2 * mm + 1]);

        // stage rows [8h,8h+8) of col j into padded transpose buffer
        {
            u64* yc = (u64*)(Ys + j * YP + h * 8);
#pragma unroll
            for (int mm = 0; mm < 4; mm++) yc[mm] = zst[mm];
        }
        __syncwarp();

        // coalesced write of Y_t (1KB contiguous) by all 32 lanes
        {
            float* out = Y + base0 + t * STEP_STRIDE;
            float4 v;
            int i = e0a >> 4, c0 = e0a & 15;
            v.x = Ys[(c0 + 0) * YP + i];
            v.y = Ys[(c0 + 1) * YP + i];
            v.z = Ys[(c0 + 2) * YP + i];
            v.w = Ys[(c0 + 3) * YP + i];
            *(float4*)(out + e0a) = v;
            i = e0b >> 4; c0 = e0b & 15;
            v.x = Ys[(c0 + 0) * YP + i];
            v.y = Ys[(c0 + 1) * YP + i];
            v.z = Ys[(c0 + 2) * YP + i];
            v.w = Ys[(c0 + 3) * YP + i];
            *(float4*)(out + e0b) = v;
        }
    }
}

// ============================================================================
extern "C" void kernel_launch(void* const* d_in, const int* in_sizes, int n_in,
                              void* d_out, int out_size)
{
    const float* A = (const float*)d_in[0];
    const float* X = (const float*)d_in[1];
    float* Y = (float*)d_out;

    phase1_kernel<<<TOTCHUNK / 2, 64>>>(A, X);
    phase2_kernel<<<CHAINS, 32>>>();
    phase3_kernel<<<TOTCHUNK / 2, 64>>>(A, X, Y);
}